// round 13
// baseline (speedup 1.0000x reference)
#include <cuda_runtime.h>
#include <cuda_fp16.h>
#include <cstddef>

#define N_USER  100000
#define N_ITEM  50000
#define N_NODES 150000
#define EMB     64
#define N_EDGES 4000000
#define BATCH   4096
#define PW_INV_LAYERS 0.25f   // 1/(N_LAYERS+1)
#define TB 256
#define NBLK ((N_NODES + TB - 1) / TB)   // 586 scan blocks

// ---- device-global scratch (allocation-free) ----
__device__ __half g_c0[(size_t)N_NODES * EMB];
__device__ __half g_c1[(size_t)N_NODES * EMB];
__device__ __half g_c2[(size_t)N_NODES * EMB];
__device__ int    g_cnt   [N_NODES];        // zero-init; re-zeroed by k_scan3
__device__ int    g_fill  [N_NODES];
__device__ int    g_rowptr[N_NODES + 1];
__device__ int    g_bsum  [1024];
__device__ int2   g_perm  [N_EDGES];        // (col, val as duplicated half2) 32 MB

// ---------------------------------------------------------------------------
// init + hist fused (scalar; validated R8 config)
// ---------------------------------------------------------------------------
__global__ void k_init_hist(const float* __restrict__ ue,
                            const float* __restrict__ ie,
                            const int*   __restrict__ rows) {
    int i = blockIdx.x * blockDim.x + threadIdx.x;
    if (i < N_EDGES)
        atomicAdd(&g_cnt[__ldg(rows + i)], 1);
    if (i < N_NODES * 32) {
        const float2* u2 = (const float2*)ue;
        const float2* i2 = (const float2*)ie;
        float2 v = (i < N_USER * 32) ? u2[i] : i2[i - N_USER * 32];
        ((half2*)g_c0)[i] = __floats2half2_rn(v.x, v.y);
    }
}

// ---------------------------------------------------------------------------
// CSR scan a: per-block sums
// ---------------------------------------------------------------------------
__global__ void k_scan1() {
    __shared__ int sh[TB];
    int i = blockIdx.x * TB + threadIdx.x;
    int c = (i < N_NODES) ? g_cnt[i] : 0;
    sh[threadIdx.x] = c; __syncthreads();
    for (int off = TB / 2; off > 0; off >>= 1) {
        if (threadIdx.x < off) sh[threadIdx.x] += sh[threadIdx.x + off];
        __syncthreads();
    }
    if (threadIdx.x == 0) g_bsum[blockIdx.x] = sh[0];
}

// ---------------------------------------------------------------------------
// CSR scan b: exclusive scan of block sums (single block)
// ---------------------------------------------------------------------------
__global__ void k_scan2() {
    __shared__ int sh[1024];
    int t = threadIdx.x;
    int v = (t < NBLK) ? g_bsum[t] : 0;
    sh[t] = v; __syncthreads();
    for (int off = 1; off < 1024; off <<= 1) {
        int add = (t >= off) ? sh[t - off] : 0;
        __syncthreads();
        sh[t] += add;
        __syncthreads();
    }
    if (t < NBLK) g_bsum[t] = sh[t] - v;   // exclusive
}

// ---------------------------------------------------------------------------
// CSR scan c: row_ptr + fill cursors; re-zeroes g_cnt for next replay
// ---------------------------------------------------------------------------
__global__ void k_scan3() {
    __shared__ int sh[TB];
    int i = blockIdx.x * TB + threadIdx.x;
    int c = (i < N_NODES) ? g_cnt[i] : 0;
    sh[threadIdx.x] = c; __syncthreads();
    for (int off = 1; off < TB; off <<= 1) {
        int add = (threadIdx.x >= off) ? sh[threadIdx.x - off] : 0;
        __syncthreads();
        sh[threadIdx.x] += add;
        __syncthreads();
    }
    int excl = sh[threadIdx.x] - c + g_bsum[blockIdx.x];
    if (i < N_NODES) { g_rowptr[i] = excl; g_fill[i] = excl; g_cnt[i] = 0; }
    if (i == 0) g_rowptr[N_NODES] = N_EDGES;
}

// ---------------------------------------------------------------------------
// CSR build: permute into row-grouped order; val stored as duplicated half2
// ---------------------------------------------------------------------------
__global__ void k_permute(const int*   __restrict__ rows,
                          const int*   __restrict__ cols,
                          const float* __restrict__ vals) {
    int e = blockIdx.x * blockDim.x + threadIdx.x;
    if (e >= N_EDGES) return;
    int r = __ldg(rows + e);
    int idx = atomicAdd(&g_fill[r], 1);
    unsigned h = (unsigned)__half_as_ushort(__float2half_rn(__ldg(vals + e)));
    g_perm[idx] = make_int2(__ldg(cols + e), (int)(h * 0x10001u));
}

// ---------------------------------------------------------------------------
// Warp-level row accumulation core, de-padded HFMA2 edition:
// - stage up to 64 (col, half2-val) entries per step (2 predicated LDGs,
//   one __syncwarp pair)
// - dynamic inner loop over ceil(n/2) int4 edge-pairs, #pragma unroll 4
//   (8 gather LDGs in flight) -> near-zero padded gathers (one (0,0) pad
//   only for odd n; gathers L1-hot row 0 with weight 0)
// - half2 accumulator per <=64-edge step, flushed to fp32
// ---------------------------------------------------------------------------
__device__ __forceinline__ float2 row_accumulate(const __half* __restrict__ src,
                                                 int beg, int end, int lane,
                                                 int2* __restrict__ slab) {
    float2 s = make_float2(0.f, 0.f);
    for (int base = beg; base < end; base += 64) {
        int n = end - base;
        if (n > 64) n = 64;
        int2 ev0 = make_int2(0, 0);
        int2 ev1 = make_int2(0, 0);
        if (lane < n)      ev0 = __ldg(&g_perm[base + lane]);
        if (lane + 32 < n) ev1 = __ldg(&g_perm[base + lane + 32]);
        __syncwarp();
        slab[lane]      = ev0;
        slab[lane + 32] = ev1;
        __syncwarp();
        half2 a0 = __float2half2_rn(0.f);
        int np = (n + 1) >> 1;          // edge-pairs
        const int4* slab4 = (const int4*)slab;
        #pragma unroll 4
        for (int j = 0; j < np; j++) {
            int4 e2 = slab4[j];
            half2 v0 = *(half2*)&e2.y;
            half2 v1 = *(half2*)&e2.w;
            half2 x0 = *(const half2*)(src + (size_t)e2.x * EMB + lane * 2);
            half2 x1 = *(const half2*)(src + (size_t)e2.z * EMB + lane * 2);
            a0 = __hfma2(v0, x0, a0);
            a0 = __hfma2(v1, x1, a0);
        }
        float2 a = __half22float2(a0);
        s.x += a.x; s.y += a.y;
        __syncwarp();
    }
    return s;
}

// ---------------------------------------------------------------------------
// full layer: one warp per row, atomic-free pull
// ---------------------------------------------------------------------------
template <int APPLY_POP>
__global__ void __launch_bounds__(TB)
k_layer(const __half* __restrict__ src,
        __half*       __restrict__ dst,
        const float*  __restrict__ upi,
        const float*  __restrict__ ipi) {
    __shared__ __align__(16) int2 sh[TB / 32][64];
    int gid  = blockIdx.x * blockDim.x + threadIdx.x;
    int row  = gid >> 5;
    int lane = gid & 31;
    int wid  = threadIdx.x >> 5;
    if (row >= N_NODES) return;

    int beg = __ldg(&g_rowptr[row]);
    int end = __ldg(&g_rowptr[row + 1]);

    float2 s = row_accumulate(src, beg, end, lane, sh[wid]);

    if (APPLY_POP) {
        float sc = (row < N_USER) ? __ldg(upi + row) : __ldg(ipi + (row - N_USER));
        s.x *= sc; s.y *= sc;
    }

    ((half2*)dst)[(size_t)row * 32 + lane] = __floats2half2_rn(s.x, s.y);
}

// ---------------------------------------------------------------------------
// fused layer-3 + gather: one warp per batch slot; c3 computed in registers
// for the ~12K sampled rows only.
//   out[sec]   = 0.25*(emb + pw*(c1+c2+c3))   sec 0..2
//   out[3+sec] = emb
// ---------------------------------------------------------------------------
__global__ void __launch_bounds__(TB)
k_l3_gather(const float* __restrict__ ue,
            const float* __restrict__ ie,
            const float* __restrict__ pwp,
            const int*   __restrict__ users,
            const int*   __restrict__ pos,
            const int*   __restrict__ neg,
            float* __restrict__ out) {
    __shared__ __align__(16) int2 sh[TB / 32][64];
    int gid  = blockIdx.x * blockDim.x + threadIdx.x;
    int w    = gid >> 5;
    int lane = gid & 31;
    int wid  = threadIdx.x >> 5;
    if (w >= 3 * BATCH) return;
    int sec = w / BATCH;
    int b   = w - sec * BATCH;

    int node; const float* emb;
    if (sec == 0)      { int u = __ldg(users + b); node = u;          emb = ue + (size_t)u * EMB; }
    else if (sec == 1) { int p = __ldg(pos + b);   node = N_USER + p; emb = ie + (size_t)p * EMB; }
    else               { int p = __ldg(neg + b);   node = N_USER + p; emb = ie + (size_t)p * EMB; }

    int beg = __ldg(&g_rowptr[node]);
    int end = __ldg(&g_rowptr[node + 1]);
    float2 s = row_accumulate(g_c2, beg, end, lane, sh[wid]);

    float pw = __ldg(pwp);
    size_t off = (size_t)node * 32 + lane;
    float2 e  = ((const float2*)emb)[lane];
    float2 c1 = __half22float2(((const half2*)g_c1)[off]);
    float2 c2 = __half22float2(((const half2*)g_c2)[off]);

    float2 o;
    o.x = PW_INV_LAYERS * (e.x + pw * (c1.x + c2.x + s.x));
    o.y = PW_INV_LAYERS * (e.y + pw * (c1.y + c2.y + s.y));

    size_t slot = (size_t)b * 32 + lane;
    ((float2*)out)[(size_t)sec * BATCH * 32 + slot]       = o;
    ((float2*)out)[(size_t)(3 + sec) * BATCH * 32 + slot] = e;
}

// ---------------------------------------------------------------------------
// kernel_launch
// Inputs: user_emb, item_emb, edge_rows, edge_cols, edge_vals,
//         user_pop_inv, item_pop_inv, popularity_weight, users, pos, neg
// ---------------------------------------------------------------------------
extern "C" void kernel_launch(void* const* d_in, const int* in_sizes, int n_in,
                              void* d_out, int out_size) {
    const float* ue    = (const float*)d_in[0];
    const float* ie    = (const float*)d_in[1];
    const int*   erow  = (const int*)  d_in[2];
    const int*   ecol  = (const int*)  d_in[3];
    const float* eval_ = (const float*)d_in[4];
    const float* upi   = (const float*)d_in[5];
    const float* ipi   = (const float*)d_in[6];
    const float* pwp   = (const float*)d_in[7];
    const int*   users = (const int*)  d_in[8];
    const int*   pos   = (const int*)  d_in[9];
    const int*   neg   = (const int*)  d_in[10];
    float* out = (float*)d_out;

    __half *c0, *c1, *c2;
    cudaGetSymbolAddress((void**)&c0, g_c0);
    cudaGetSymbolAddress((void**)&c1, g_c1);
    cudaGetSymbolAddress((void**)&c2, g_c2);

    const int inith_grid    = (N_NODES * 32 + TB - 1) / TB;
    const int edge_grid     = (N_EDGES + TB - 1) / TB;
    const int row_warp_grid = (N_NODES * 32 + TB - 1) / TB;   // 1 warp/row
    const int l3g_grid      = (3 * BATCH * 32 + TB - 1) / TB;

    // init + CSR build (every replay; deterministic)
    k_init_hist<<<inith_grid, TB>>>(ue, ie, erow);
    k_scan1<<<NBLK, TB>>>();
    k_scan2<<<1, 1024>>>();
    k_scan3<<<NBLK, TB>>>();
    k_permute<<<edge_grid, TB>>>(erow, ecol, eval_);

    // layers 1 and 2 over all nodes (atomic-free pull, HFMA2, de-padded)
    k_layer<1><<<row_warp_grid, TB>>>(c0, c1, upi, ipi);
    k_layer<0><<<row_warp_grid, TB>>>(c1, c2, upi, ipi);

    // layer 3 restricted to sampled rows, fused with output gather
    k_l3_gather<<<l3g_grid, TB>>>(ue, ie, pwp, users, pos, neg, out);

    (void)in_sizes; (void)n_in; (void)out_size;
}

// round 14
// speedup vs baseline: 1.0081x; 1.0081x over previous
#include <cuda_runtime.h>
#include <cuda_fp16.h>
#include <cstddef>

#define N_USER  100000
#define N_ITEM  50000
#define N_NODES 150000
#define EMB     64
#define N_EDGES 4000000
#define BATCH   4096
#define PW_INV_LAYERS 0.25f   // 1/(N_LAYERS+1)
#define TB 256
#define NBLK ((N_NODES + TB - 1) / TB)   // 586 scan blocks

// ---- device-global scratch (allocation-free) ----
__device__ __half g_c0[(size_t)N_NODES * EMB];
__device__ __half g_c1[(size_t)N_NODES * EMB];
__device__ __half g_c2[(size_t)N_NODES * EMB];
__device__ int    g_cnt   [N_NODES];        // zero-init; re-zeroed by k_scan3
__device__ int    g_rank  [N_EDGES];        // within-row rank of each edge, 16 MB
__device__ int    g_rowptr[N_NODES + 1];
__device__ int    g_bsum  [1024];
__device__ int2   g_perm  [N_EDGES];        // (col, val as duplicated half2) 32 MB

// ---------------------------------------------------------------------------
// init + hist fused; the histogram atomic's RETURN VALUE is kept as the
// edge's within-row rank -> permute needs no atomics at all.
// ---------------------------------------------------------------------------
__global__ void k_init_hist(const float* __restrict__ ue,
                            const float* __restrict__ ie,
                            const int*   __restrict__ rows) {
    int i = blockIdx.x * blockDim.x + threadIdx.x;
    if (i < N_EDGES)
        g_rank[i] = atomicAdd(&g_cnt[__ldg(rows + i)], 1);
    if (i < N_NODES * 32) {
        const float2* u2 = (const float2*)ue;
        const float2* i2 = (const float2*)ie;
        float2 v = (i < N_USER * 32) ? u2[i] : i2[i - N_USER * 32];
        ((half2*)g_c0)[i] = __floats2half2_rn(v.x, v.y);
    }
}

// ---------------------------------------------------------------------------
// CSR scan a: per-block sums
// ---------------------------------------------------------------------------
__global__ void k_scan1() {
    __shared__ int sh[TB];
    int i = blockIdx.x * TB + threadIdx.x;
    int c = (i < N_NODES) ? g_cnt[i] : 0;
    sh[threadIdx.x] = c; __syncthreads();
    for (int off = TB / 2; off > 0; off >>= 1) {
        if (threadIdx.x < off) sh[threadIdx.x] += sh[threadIdx.x + off];
        __syncthreads();
    }
    if (threadIdx.x == 0) g_bsum[blockIdx.x] = sh[0];
}

// ---------------------------------------------------------------------------
// CSR scan b: exclusive scan of block sums (single block)
// ---------------------------------------------------------------------------
__global__ void k_scan2() {
    __shared__ int sh[1024];
    int t = threadIdx.x;
    int v = (t < NBLK) ? g_bsum[t] : 0;
    sh[t] = v; __syncthreads();
    for (int off = 1; off < 1024; off <<= 1) {
        int add = (t >= off) ? sh[t - off] : 0;
        __syncthreads();
        sh[t] += add;
        __syncthreads();
    }
    if (t < NBLK) g_bsum[t] = sh[t] - v;   // exclusive
}

// ---------------------------------------------------------------------------
// CSR scan c: row_ptr; re-zeroes g_cnt for next replay
// ---------------------------------------------------------------------------
__global__ void k_scan3() {
    __shared__ int sh[TB];
    int i = blockIdx.x * TB + threadIdx.x;
    int c = (i < N_NODES) ? g_cnt[i] : 0;
    sh[threadIdx.x] = c; __syncthreads();
    for (int off = 1; off < TB; off <<= 1) {
        int add = (threadIdx.x >= off) ? sh[threadIdx.x - off] : 0;
        __syncthreads();
        sh[threadIdx.x] += add;
        __syncthreads();
    }
    int excl = sh[threadIdx.x] - c + g_bsum[blockIdx.x];
    if (i < N_NODES) { g_rowptr[i] = excl; g_cnt[i] = 0; }
    if (i == 0) g_rowptr[N_NODES] = N_EDGES;
}

// ---------------------------------------------------------------------------
// CSR build: atomic-free permute using precomputed ranks.
// dst = rowptr[row] + rank  (address ready after 2 independent loads ->
// scattered stores pipeline with full MLP)
// ---------------------------------------------------------------------------
__global__ void k_permute(const int*   __restrict__ rows,
                          const int*   __restrict__ cols,
                          const float* __restrict__ vals) {
    int e = blockIdx.x * blockDim.x + threadIdx.x;
    if (e >= N_EDGES) return;
    int r   = __ldg(rows + e);
    int idx = __ldg(&g_rowptr[r]) + g_rank[e];
    unsigned h = (unsigned)__half_as_ushort(__float2half_rn(__ldg(vals + e)));
    g_perm[idx] = make_int2(__ldg(cols + e), (int)(h * 0x10001u));
}

// ---------------------------------------------------------------------------
// Warp-level row accumulation core (R10-validated fixed-32 HFMA2 version):
// - stage 32 (col, half2-val) entries in the warp's smem slab
// - FIXED 16-trip fully-unrolled loop, 2 edges per LDS.128 -> straight-line
//   MLP block (this beat the de-padded dynamic loop by 12 us in R13)
// - half2 accumulator per chunk, flushed to fp32
// - inactive entries (0,0): gather L1-hot row 0 with half2 weight 0
// ---------------------------------------------------------------------------
__device__ __forceinline__ float2 row_accumulate(const __half* __restrict__ src,
                                                 int beg, int end, int lane,
                                                 int2* __restrict__ slab) {
    float2 s = make_float2(0.f, 0.f);
    for (int base = beg; base < end; base += 32) {
        int n = end - base;
        int2 ev = make_int2(0, 0);
        if (lane < n) ev = __ldg(&g_perm[base + lane]);
        __syncwarp();
        slab[lane] = ev;
        __syncwarp();
        half2 a0 = __float2half2_rn(0.f);
        const int4* slab4 = (const int4*)slab;
        #pragma unroll
        for (int j = 0; j < 16; j++) {
            int4 e2 = slab4[j];
            half2 v0 = *(half2*)&e2.y;
            half2 v1 = *(half2*)&e2.w;
            half2 x0 = *(const half2*)(src + (size_t)e2.x * EMB + lane * 2);
            half2 x1 = *(const half2*)(src + (size_t)e2.z * EMB + lane * 2);
            a0 = __hfma2(v0, x0, a0);
            a0 = __hfma2(v1, x1, a0);
        }
        float2 a = __half22float2(a0);
        s.x += a.x; s.y += a.y;
        __syncwarp();
    }
    return s;
}

// ---------------------------------------------------------------------------
// full layer: one warp per row, atomic-free pull
// ---------------------------------------------------------------------------
template <int APPLY_POP>
__global__ void __launch_bounds__(TB)
k_layer(const __half* __restrict__ src,
        __half*       __restrict__ dst,
        const float*  __restrict__ upi,
        const float*  __restrict__ ipi) {
    __shared__ __align__(16) int2 sh[TB / 32][32];
    int gid  = blockIdx.x * blockDim.x + threadIdx.x;
    int row  = gid >> 5;
    int lane = gid & 31;
    int wid  = threadIdx.x >> 5;
    if (row >= N_NODES) return;

    int beg = __ldg(&g_rowptr[row]);
    int end = __ldg(&g_rowptr[row + 1]);

    float2 s = row_accumulate(src, beg, end, lane, sh[wid]);

    if (APPLY_POP) {
        float sc = (row < N_USER) ? __ldg(upi + row) : __ldg(ipi + (row - N_USER));
        s.x *= sc; s.y *= sc;
    }

    ((half2*)dst)[(size_t)row * 32 + lane] = __floats2half2_rn(s.x, s.y);
}

// ---------------------------------------------------------------------------
// fused layer-3 + gather: one warp per batch slot; c3 computed in registers
// for the ~12K sampled rows only.
//   out[sec]   = 0.25*(emb + pw*(c1+c2+c3))   sec 0..2
//   out[3+sec] = emb
// ---------------------------------------------------------------------------
__global__ void __launch_bounds__(TB)
k_l3_gather(const float* __restrict__ ue,
            const float* __restrict__ ie,
            const float* __restrict__ pwp,
            const int*   __restrict__ users,
            const int*   __restrict__ pos,
            const int*   __restrict__ neg,
            float* __restrict__ out) {
    __shared__ __align__(16) int2 sh[TB / 32][32];
    int gid  = blockIdx.x * blockDim.x + threadIdx.x;
    int w    = gid >> 5;
    int lane = gid & 31;
    int wid  = threadIdx.x >> 5;
    if (w >= 3 * BATCH) return;
    int sec = w / BATCH;
    int b   = w - sec * BATCH;

    int node; const float* emb;
    if (sec == 0)      { int u = __ldg(users + b); node = u;          emb = ue + (size_t)u * EMB; }
    else if (sec == 1) { int p = __ldg(pos + b);   node = N_USER + p; emb = ie + (size_t)p * EMB; }
    else               { int p = __ldg(neg + b);   node = N_USER + p; emb = ie + (size_t)p * EMB; }

    int beg = __ldg(&g_rowptr[node]);
    int end = __ldg(&g_rowptr[node + 1]);
    float2 s = row_accumulate(g_c2, beg, end, lane, sh[wid]);

    float pw = __ldg(pwp);
    size_t off = (size_t)node * 32 + lane;
    float2 e  = ((const float2*)emb)[lane];
    float2 c1 = __half22float2(((const half2*)g_c1)[off]);
    float2 c2 = __half22float2(((const half2*)g_c2)[off]);

    float2 o;
    o.x = PW_INV_LAYERS * (e.x + pw * (c1.x + c2.x + s.x));
    o.y = PW_INV_LAYERS * (e.y + pw * (c1.y + c2.y + s.y));

    size_t slot = (size_t)b * 32 + lane;
    ((float2*)out)[(size_t)sec * BATCH * 32 + slot]       = o;
    ((float2*)out)[(size_t)(3 + sec) * BATCH * 32 + slot] = e;
}

// ---------------------------------------------------------------------------
// kernel_launch
// Inputs: user_emb, item_emb, edge_rows, edge_cols, edge_vals,
//         user_pop_inv, item_pop_inv, popularity_weight, users, pos, neg
// ---------------------------------------------------------------------------
extern "C" void kernel_launch(void* const* d_in, const int* in_sizes, int n_in,
                              void* d_out, int out_size) {
    const float* ue    = (const float*)d_in[0];
    const float* ie    = (const float*)d_in[1];
    const int*   erow  = (const int*)  d_in[2];
    const int*   ecol  = (const int*)  d_in[3];
    const float* eval_ = (const float*)d_in[4];
    const float* upi   = (const float*)d_in[5];
    const float* ipi   = (const float*)d_in[6];
    const float* pwp   = (const float*)d_in[7];
    const int*   users = (const int*)  d_in[8];
    const int*   pos   = (const int*)  d_in[9];
    const int*   neg   = (const int*)  d_in[10];
    float* out = (float*)d_out;

    __half *c0, *c1, *c2;
    cudaGetSymbolAddress((void**)&c0, g_c0);
    cudaGetSymbolAddress((void**)&c1, g_c1);
    cudaGetSymbolAddress((void**)&c2, g_c2);

    const int inith_grid    = (N_NODES * 32 + TB - 1) / TB;   // covers 4M edges too
    const int edge_grid     = (N_EDGES + TB - 1) / TB;
    const int row_warp_grid = (N_NODES * 32 + TB - 1) / TB;   // 1 warp/row
    const int l3g_grid      = (3 * BATCH * 32 + TB - 1) / TB;

    // init + CSR build (every replay; deterministic)
    k_init_hist<<<inith_grid, TB>>>(ue, ie, erow);
    k_scan1<<<NBLK, TB>>>();
    k_scan2<<<1, 1024>>>();
    k_scan3<<<NBLK, TB>>>();
    k_permute<<<edge_grid, TB>>>(erow, ecol, eval_);

    // layers 1 and 2 over all nodes (atomic-free pull, fixed-32 HFMA2 core)
    k_layer<1><<<row_warp_grid, TB>>>(c0, c1, upi, ipi);
    k_layer<0><<<row_warp_grid, TB>>>(c1, c2, upi, ipi);

    // layer 3 restricted to sampled rows, fused with output gather
    k_l3_gather<<<l3g_grid, TB>>>(ue, ie, pwp, users, pos, neg, out);

    (void)in_sizes; (void)n_in; (void)out_size;
}

// round 15
// speedup vs baseline: 1.1369x; 1.1278x over previous
#include <cuda_runtime.h>
#include <cuda_fp16.h>
#include <cstddef>

#define N_USER  100000
#define N_ITEM  50000
#define N_NODES 150000
#define EMB     64
#define N_EDGES 4000000
#define BATCH   4096
#define PW_INV_LAYERS 0.25f   // 1/(N_LAYERS+1)
#define TB 256
#define NBLK ((N_NODES + TB - 1) / TB)   // 586 scan blocks

// ---- device-global scratch (allocation-free) ----
__device__ __half g_c0[(size_t)N_NODES * EMB];
__device__ __half g_c1[(size_t)N_NODES * EMB];
__device__ __half g_c2[(size_t)N_NODES * EMB];
__device__ int    g_cnt   [N_NODES];        // zero-init; re-zeroed by k_scan3
__device__ int    g_fill  [N_NODES];
__device__ int    g_rowptr[N_NODES + 1];
__device__ int    g_bsum  [1024];
__device__ int2   g_perm  [N_EDGES];        // (col, val as duplicated half2) 32 MB

// ---------------------------------------------------------------------------
// init + hist fused (R10-validated scalar version)
// ---------------------------------------------------------------------------
__global__ void k_init_hist(const float* __restrict__ ue,
                            const float* __restrict__ ie,
                            const int*   __restrict__ rows) {
    int i = blockIdx.x * blockDim.x + threadIdx.x;
    if (i < N_EDGES)
        atomicAdd(&g_cnt[__ldg(rows + i)], 1);
    if (i < N_NODES * 32) {
        const float2* u2 = (const float2*)ue;
        const float2* i2 = (const float2*)ie;
        float2 v = (i < N_USER * 32) ? u2[i] : i2[i - N_USER * 32];
        ((half2*)g_c0)[i] = __floats2half2_rn(v.x, v.y);
    }
}

// ---------------------------------------------------------------------------
// CSR scan a: per-block sums
// ---------------------------------------------------------------------------
__global__ void k_scan1() {
    __shared__ int sh[TB];
    int i = blockIdx.x * TB + threadIdx.x;
    int c = (i < N_NODES) ? g_cnt[i] : 0;
    sh[threadIdx.x] = c; __syncthreads();
    for (int off = TB / 2; off > 0; off >>= 1) {
        if (threadIdx.x < off) sh[threadIdx.x] += sh[threadIdx.x + off];
        __syncthreads();
    }
    if (threadIdx.x == 0) g_bsum[blockIdx.x] = sh[0];
}

// ---------------------------------------------------------------------------
// CSR scan b: exclusive scan of block sums (single block)
// ---------------------------------------------------------------------------
__global__ void k_scan2() {
    __shared__ int sh[1024];
    int t = threadIdx.x;
    int v = (t < NBLK) ? g_bsum[t] : 0;
    sh[t] = v; __syncthreads();
    for (int off = 1; off < 1024; off <<= 1) {
        int add = (t >= off) ? sh[t - off] : 0;
        __syncthreads();
        sh[t] += add;
        __syncthreads();
    }
    if (t < NBLK) g_bsum[t] = sh[t] - v;   // exclusive
}

// ---------------------------------------------------------------------------
// CSR scan c: row_ptr + fill cursors; re-zeroes g_cnt for next replay
// ---------------------------------------------------------------------------
__global__ void k_scan3() {
    __shared__ int sh[TB];
    int i = blockIdx.x * TB + threadIdx.x;
    int c = (i < N_NODES) ? g_cnt[i] : 0;
    sh[threadIdx.x] = c; __syncthreads();
    for (int off = 1; off < TB; off <<= 1) {
        int add = (threadIdx.x >= off) ? sh[threadIdx.x - off] : 0;
        __syncthreads();
        sh[threadIdx.x] += add;
        __syncthreads();
    }
    int excl = sh[threadIdx.x] - c + g_bsum[blockIdx.x];
    if (i < N_NODES) { g_rowptr[i] = excl; g_fill[i] = excl; g_cnt[i] = 0; }
    if (i == 0) g_rowptr[N_NODES] = N_EDGES;
}

// ---------------------------------------------------------------------------
// CSR build: fill-cursor permute (R10-validated; beats rank-capture by 10us)
// ---------------------------------------------------------------------------
__global__ void k_permute(const int*   __restrict__ rows,
                          const int*   __restrict__ cols,
                          const float* __restrict__ vals) {
    int e = blockIdx.x * blockDim.x + threadIdx.x;
    if (e >= N_EDGES) return;
    int r = __ldg(rows + e);
    int idx = atomicAdd(&g_fill[r], 1);
    unsigned h = (unsigned)__half_as_ushort(__float2half_rn(__ldg(vals + e)));
    g_perm[idx] = make_int2(__ldg(cols + e), (int)(h * 0x10001u));
}

// ---------------------------------------------------------------------------
// Warp-level row accumulation, half-warp-paired edition:
// - stage 32 (col, half2-val) entries in the warp's smem slab (as R10)
// - FIXED 16-trip fully-unrolled loop; per trip the two HALF-WARPS process
//   two different edges: lane owns an 8B slice (sub=lane&15) of its edge's
//   row -> per 2 edges: 1 LDS.64 + 1 LDG.64 + 2 HFMA2 (vs 1+2+2 in R10;
//   LDG instruction count halved)
// - per-lane half2 accumulators (4 halves), flushed to fp32 per chunk;
//   one cross-half-warp shfl_xor(16) combine at the end
// - pad entries (0,0): gather L1-hot row 0 with weight 0 (validated scheme)
// Returns float4 = fp32 sums for halves [4*sub, 4*sub+4) (valid in all lanes).
// ---------------------------------------------------------------------------
__device__ __forceinline__ float4 row_accumulate(const __half* __restrict__ src,
                                                 int beg, int end, int lane,
                                                 int2* __restrict__ slab) {
    int hw  = lane >> 4;       // which half-warp (selects edge of the pair)
    int sub = lane & 15;       // 8B slice index within the row
    float2 s0 = make_float2(0.f, 0.f);
    float2 s1 = make_float2(0.f, 0.f);
    for (int base = beg; base < end; base += 32) {
        int n = end - base;
        int2 ev = make_int2(0, 0);
        if (lane < n) ev = __ldg(&g_perm[base + lane]);
        __syncwarp();
        slab[lane] = ev;
        __syncwarp();
        half2 a0 = __float2half2_rn(0.f);
        half2 a1 = __float2half2_rn(0.f);
        #pragma unroll
        for (int j = 0; j < 16; j++) {
            int2 e = slab[2 * j + hw];
            half2 v = *(half2*)&e.y;
            int2 xi = *((const int2*)(src + (size_t)e.x * EMB) + sub);
            half2 x0 = *(half2*)&xi.x;
            half2 x1 = *(half2*)&xi.y;
            a0 = __hfma2(v, x0, a0);
            a1 = __hfma2(v, x1, a1);
        }
        float2 f0 = __half22float2(a0);
        float2 f1 = __half22float2(a1);
        s0.x += f0.x; s0.y += f0.y;
        s1.x += f1.x; s1.y += f1.y;
        __syncwarp();
    }
    // combine the two half-warps' partial sums (each covered its own edges)
    s0.x += __shfl_xor_sync(0xffffffffu, s0.x, 16);
    s0.y += __shfl_xor_sync(0xffffffffu, s0.y, 16);
    s1.x += __shfl_xor_sync(0xffffffffu, s1.x, 16);
    s1.y += __shfl_xor_sync(0xffffffffu, s1.y, 16);
    return make_float4(s0.x, s0.y, s1.x, s1.y);
}

// ---------------------------------------------------------------------------
// full layer: one warp per row, atomic-free pull
// ---------------------------------------------------------------------------
template <int APPLY_POP>
__global__ void __launch_bounds__(TB)
k_layer(const __half* __restrict__ src,
        __half*       __restrict__ dst,
        const float*  __restrict__ upi,
        const float*  __restrict__ ipi) {
    __shared__ __align__(16) int2 sh[TB / 32][32];
    int gid  = blockIdx.x * blockDim.x + threadIdx.x;
    int row  = gid >> 5;
    int lane = gid & 31;
    int wid  = threadIdx.x >> 5;
    if (row >= N_NODES) return;

    int beg = __ldg(&g_rowptr[row]);
    int end = __ldg(&g_rowptr[row + 1]);

    float4 s = row_accumulate(src, beg, end, lane, sh[wid]);

    if (APPLY_POP) {
        float sc = (row < N_USER) ? __ldg(upi + row) : __ldg(ipi + (row - N_USER));
        s.x *= sc; s.y *= sc; s.z *= sc; s.w *= sc;
    }

    if (lane < 16) {
        half2 h0 = __floats2half2_rn(s.x, s.y);
        half2 h1 = __floats2half2_rn(s.z, s.w);
        int2 pk = make_int2(*(int*)&h0, *(int*)&h1);
        ((int2*)(dst + (size_t)row * EMB))[lane] = pk;   // lane==sub here
    }
}

// ---------------------------------------------------------------------------
// fused layer-3 + gather: one warp per batch slot; c3 computed in registers
// for the ~12K sampled rows only.
//   out[sec]   = 0.25*(emb + pw*(c1+c2+c3))   sec 0..2
//   out[3+sec] = emb
// lanes 0-15 each own a float4 (4 floats) slice of the 64-float row.
// ---------------------------------------------------------------------------
__global__ void __launch_bounds__(TB)
k_l3_gather(const float* __restrict__ ue,
            const float* __restrict__ ie,
            const float* __restrict__ pwp,
            const int*   __restrict__ users,
            const int*   __restrict__ pos,
            const int*   __restrict__ neg,
            float* __restrict__ out) {
    __shared__ __align__(16) int2 sh[TB / 32][32];
    int gid  = blockIdx.x * blockDim.x + threadIdx.x;
    int w    = gid >> 5;
    int lane = gid & 31;
    int wid  = threadIdx.x >> 5;
    if (w >= 3 * BATCH) return;
    int sec = w / BATCH;
    int b   = w - sec * BATCH;

    int node; const float* emb;
    if (sec == 0)      { int u = __ldg(users + b); node = u;          emb = ue + (size_t)u * EMB; }
    else if (sec == 1) { int p = __ldg(pos + b);   node = N_USER + p; emb = ie + (size_t)p * EMB; }
    else               { int p = __ldg(neg + b);   node = N_USER + p; emb = ie + (size_t)p * EMB; }

    int beg = __ldg(&g_rowptr[node]);
    int end = __ldg(&g_rowptr[node + 1]);
    float4 s = row_accumulate(g_c2, beg, end, lane, sh[wid]);

    if (lane < 16) {
        float pw = __ldg(pwp);
        int sub = lane;
        float4 e4 = ((const float4*)emb)[sub];
        int2 c1i = *((const int2*)(g_c1 + (size_t)node * EMB) + sub);
        int2 c2i = *((const int2*)(g_c2 + (size_t)node * EMB) + sub);
        float2 c1a = __half22float2(*(half2*)&c1i.x);
        float2 c1b = __half22float2(*(half2*)&c1i.y);
        float2 c2a = __half22float2(*(half2*)&c2i.x);
        float2 c2b = __half22float2(*(half2*)&c2i.y);

        float4 o;
        o.x = PW_INV_LAYERS * (e4.x + pw * (c1a.x + c2a.x + s.x));
        o.y = PW_INV_LAYERS * (e4.y + pw * (c1a.y + c2a.y + s.y));
        o.z = PW_INV_LAYERS * (e4.z + pw * (c1b.x + c2b.x + s.z));
        o.w = PW_INV_LAYERS * (e4.w + pw * (c1b.y + c2b.y + s.w));

        size_t slot = (size_t)b * 16 + sub;
        ((float4*)out)[(size_t)sec * BATCH * 16 + slot]       = o;   // sections 0-2
        ((float4*)out)[(size_t)(3 + sec) * BATCH * 16 + slot] = e4;  // sections 3-5
    }
}

// ---------------------------------------------------------------------------
// kernel_launch
// Inputs: user_emb, item_emb, edge_rows, edge_cols, edge_vals,
//         user_pop_inv, item_pop_inv, popularity_weight, users, pos, neg
// ---------------------------------------------------------------------------
extern "C" void kernel_launch(void* const* d_in, const int* in_sizes, int n_in,
                              void* d_out, int out_size) {
    const float* ue    = (const float*)d_in[0];
    const float* ie    = (const float*)d_in[1];
    const int*   erow  = (const int*)  d_in[2];
    const int*   ecol  = (const int*)  d_in[3];
    const float* eval_ = (const float*)d_in[4];
    const float* upi   = (const float*)d_in[5];
    const float* ipi   = (const float*)d_in[6];
    const float* pwp   = (const float*)d_in[7];
    const int*   users = (const int*)  d_in[8];
    const int*   pos   = (const int*)  d_in[9];
    const int*   neg   = (const int*)  d_in[10];
    float* out = (float*)d_out;

    __half *c0, *c1, *c2;
    cudaGetSymbolAddress((void**)&c0, g_c0);
    cudaGetSymbolAddress((void**)&c1, g_c1);
    cudaGetSymbolAddress((void**)&c2, g_c2);

    const int inith_grid    = (N_NODES * 32 + TB - 1) / TB;   // covers 4M edges too
    const int edge_grid     = (N_EDGES + TB - 1) / TB;
    const int row_warp_grid = (N_NODES * 32 + TB - 1) / TB;   // 1 warp/row
    const int l3g_grid      = (3 * BATCH * 32 + TB - 1) / TB;

    // init + CSR build (every replay; deterministic; R10-validated config)
    k_init_hist<<<inith_grid, TB>>>(ue, ie, erow);
    k_scan1<<<NBLK, TB>>>();
    k_scan2<<<1, 1024>>>();
    k_scan3<<<NBLK, TB>>>();
    k_permute<<<edge_grid, TB>>>(erow, ecol, eval_);

    // layers 1 and 2 over all nodes (half-warp-paired HFMA2 core)
    k_layer<1><<<row_warp_grid, TB>>>(c0, c1, upi, ipi);
    k_layer<0><<<row_warp_grid, TB>>>(c1, c2, upi, ipi);

    // layer 3 restricted to sampled rows, fused with output gather
    k_l3_gather<<<l3g_grid, TB>>>(ue, ie, pwp, users, pos, neg, out);

    (void)in_sizes; (void)n_in; (void)out_size;
}